// round 1
// baseline (speedup 1.0000x reference)
#include <cuda_runtime.h>
#include <cuda_bf16.h>
#include <math.h>

// Problem constants
#define BB   8
#define SS   1024
#define DD   512
#define HH   8
#define HD   64
#define DFF  2048
#define NT   (BB*SS)      // 8192 tokens
#define EPSV 1e-6f

// ---------------------------------------------------------------------------
// Scratch buffers (device globals; no allocation allowed)
// ---------------------------------------------------------------------------
__device__ float g_h  [NT*DD];
__device__ float g_q  [NT*DD];
__device__ float g_k  [NT*DD];
__device__ float g_v  [NT*DD];
__device__ float g_ctx[NT*DD];
__device__ float g_y  [NT*DD];
__device__ float g_h2 [NT*DD];
__device__ float g_ff [NT*DFF];

// ---------------------------------------------------------------------------
// RMSNorm: one block per row of 512 floats, 128 threads (float4 per thread)
// ---------------------------------------------------------------------------
__global__ void rmsnorm_kernel(const float* __restrict__ x,
                               const float* __restrict__ w,
                               float* __restrict__ o)
{
    const int row = blockIdx.x;
    const float4* xr = (const float4*)(x + (size_t)row * DD);
    const float4* wr = (const float4*)w;
    float4 v = xr[threadIdx.x];
    float ss = v.x*v.x + v.y*v.y + v.z*v.z + v.w*v.w;
    #pragma unroll
    for (int off = 16; off >= 1; off >>= 1)
        ss += __shfl_xor_sync(0xffffffffu, ss, off);
    __shared__ float sred[4];
    if ((threadIdx.x & 31) == 0) sred[threadIdx.x >> 5] = ss;
    __syncthreads();
    float tot = sred[0] + sred[1] + sred[2] + sred[3];
    float inv = rsqrtf(tot * (1.0f / DD) + EPSV);
    float4 wv = wr[threadIdx.x];
    float4 out;
    out.x = v.x * wv.x * inv;
    out.y = v.y * wv.y * inv;
    out.z = v.z * wv.z * inv;
    out.w = v.w * wv.w * inv;
    ((float4*)(o + (size_t)row * DD))[threadIdx.x] = out;
}

// ---------------------------------------------------------------------------
// SGEMM NT:  C[M,N] = A[M,K] * Bw[N,K]^T  (+ epilogue)
//   EPI 0: none   EPI 1: relu   EPI 2: += Res[M,N]
// 128x128 block tile, BK=16, 8x8 per thread, 256 threads.
// ---------------------------------------------------------------------------
template<int EPI>
__global__ void __launch_bounds__(256)
sgemm_nt(const float* __restrict__ A, const float* __restrict__ Bw,
         const float* __restrict__ Res, float* __restrict__ C,
         int M, int Nn, int K)
{
    constexpr int BM = 128, BN = 128, BK = 16;
    __shared__ float As[BK][BM];
    __shared__ float Bs[BK][BN];

    const int bm = blockIdx.y * BM;
    const int bn = blockIdx.x * BN;
    const int tid = threadIdx.x;
    const int ty = tid >> 4;        // 0..15
    const int tx = tid & 15;        // 0..15

    const float* Ag = A  + (size_t)bm * K;
    const float* Bg = Bw + (size_t)bn * K;

    float acc[8][8];
    #pragma unroll
    for (int i = 0; i < 8; i++)
        #pragma unroll
        for (int j = 0; j < 8; j++) acc[i][j] = 0.0f;

    for (int k0 = 0; k0 < K; k0 += BK) {
        // Load 128x16 A and B tiles (512 float4 each, 2 per thread)
        #pragma unroll
        for (int i = 0; i < 2; i++) {
            int idx = tid + i * 256;         // 0..511
            int r  = idx >> 2;               // 0..127
            int c4 = (idx & 3) * 4;          // 0,4,8,12
            float4 av = *(const float4*)&Ag[(size_t)r * K + k0 + c4];
            As[c4+0][r] = av.x; As[c4+1][r] = av.y;
            As[c4+2][r] = av.z; As[c4+3][r] = av.w;
            float4 bv = *(const float4*)&Bg[(size_t)r * K + k0 + c4];
            Bs[c4+0][r] = bv.x; Bs[c4+1][r] = bv.y;
            Bs[c4+2][r] = bv.z; Bs[c4+3][r] = bv.w;
        }
        __syncthreads();

        #pragma unroll
        for (int kk = 0; kk < BK; kk++) {
            float a[8], b[8];
            *(float4*)&a[0] = *(const float4*)&As[kk][ty * 8];
            *(float4*)&a[4] = *(const float4*)&As[kk][ty * 8 + 4];
            *(float4*)&b[0] = *(const float4*)&Bs[kk][tx * 8];
            *(float4*)&b[4] = *(const float4*)&Bs[kk][tx * 8 + 4];
            #pragma unroll
            for (int i = 0; i < 8; i++)
                #pragma unroll
                for (int j = 0; j < 8; j++)
                    acc[i][j] = fmaf(a[i], b[j], acc[i][j]);
        }
        __syncthreads();
    }

    // Epilogue + store (float4)
    #pragma unroll
    for (int i = 0; i < 8; i++) {
        int m = bm + ty * 8 + i;
        float* crow = C + (size_t)m * Nn + bn + tx * 8;
        const float* rrow = (EPI == 2) ? (Res + (size_t)m * Nn + bn + tx * 8) : nullptr;
        #pragma unroll
        for (int jv = 0; jv < 2; jv++) {
            float4 v;
            v.x = acc[i][jv*4+0]; v.y = acc[i][jv*4+1];
            v.z = acc[i][jv*4+2]; v.w = acc[i][jv*4+3];
            if (EPI == 1) {
                v.x = fmaxf(v.x, 0.f); v.y = fmaxf(v.y, 0.f);
                v.z = fmaxf(v.z, 0.f); v.w = fmaxf(v.w, 0.f);
            }
            if (EPI == 2) {
                float4 r = *(const float4*)&rrow[jv*4];
                v.x += r.x; v.y += r.y; v.z += r.z; v.w += r.w;
            }
            *(float4*)&crow[jv*4] = v;
        }
    }
}

// ---------------------------------------------------------------------------
// Flash attention: per (b,h) and 64-row q tile, stream 64-row K/V tiles.
// scores = q.k^T + bias (NO 1/sqrt(d)), online softmax, ctx accumulation.
// Thread layout: 16x16, each thread owns a 4x4 patch of the 64x64 tile.
// smem: Qs[64][64] | Ks[64][65] (reused for P) | Vs[64][64]
// ---------------------------------------------------------------------------
#define QS_STR 64
#define KS_STR 65
#define VS_STR 64
#define ATTN_SMEM ((64*QS_STR + 64*KS_STR + 64*VS_STR) * 4)

__global__ void __launch_bounds__(256)
attention_kernel(const float* __restrict__ q, const float* __restrict__ k,
                 const float* __restrict__ v, const float* __restrict__ bias,
                 float* __restrict__ ctx)
{
    extern __shared__ float sm[];
    float* Qs = sm;                       // 64*64
    float* Ks = sm + 64*QS_STR;           // 64*65 (also holds P)
    float* Vs = Ks + 64*KS_STR;           // 64*64

    const int q0 = blockIdx.x * 64;
    const int bh = blockIdx.y;            // b*H + h
    const int b  = bh / HH;
    const int h  = bh % HH;
    const int tid = threadIdx.x;
    const int ty = tid >> 4;              // 0..15 -> rows ty*4..+3
    const int tx = tid & 15;              // 0..15 -> cols tx*4..+3

    const float* bias_bh = bias + (size_t)bh * SS * SS;

    // Load Q tile: 64 rows x 64 cols = 1024 float4, 4 per thread
    #pragma unroll
    for (int i = 0; i < 4; i++) {
        int idx = tid + i * 256;
        int r  = idx >> 4;
        int c4 = (idx & 15) * 4;
        float4 qv = *(const float4*)&q[(size_t)(b*SS + q0 + r) * DD + h*HD + c4];
        *(float4*)&Qs[r*QS_STR + c4] = qv;
    }
    __syncthreads();

    float m_old[4], l[4], acc[4][4];
    #pragma unroll
    for (int i = 0; i < 4; i++) {
        m_old[i] = -1e30f; l[i] = 0.0f;
        #pragma unroll
        for (int j = 0; j < 4; j++) acc[i][j] = 0.0f;
    }

    for (int k0 = 0; k0 < SS; k0 += 64) {
        // Load K, V tiles
        #pragma unroll
        for (int i = 0; i < 4; i++) {
            int idx = tid + i * 256;
            int r  = idx >> 4;
            int c4 = (idx & 15) * 4;
            float4 kv = *(const float4*)&k[(size_t)(b*SS + k0 + r) * DD + h*HD + c4];
            Ks[r*KS_STR + c4+0] = kv.x; Ks[r*KS_STR + c4+1] = kv.y;
            Ks[r*KS_STR + c4+2] = kv.z; Ks[r*KS_STR + c4+3] = kv.w;
            float4 vv = *(const float4*)&v[(size_t)(b*SS + k0 + r) * DD + h*HD + c4];
            *(float4*)&Vs[r*VS_STR + c4] = vv;
        }
        __syncthreads();

        // S = Q.K^T (4x4 per thread)
        float s[4][4];
        #pragma unroll
        for (int i = 0; i < 4; i++)
            #pragma unroll
            for (int j = 0; j < 4; j++) s[i][j] = 0.0f;

        #pragma unroll 4
        for (int d = 0; d < HD; d++) {
            float qr[4], kr[4];
            #pragma unroll
            for (int i = 0; i < 4; i++) qr[i] = Qs[(ty*4+i)*QS_STR + d];
            #pragma unroll
            for (int j = 0; j < 4; j++) kr[j] = Ks[(tx*4+j)*KS_STR + d];
            #pragma unroll
            for (int i = 0; i < 4; i++)
                #pragma unroll
                for (int j = 0; j < 4; j++)
                    s[i][j] = fmaf(qr[i], kr[j], s[i][j]);
        }
        // + bias
        #pragma unroll
        for (int i = 0; i < 4; i++) {
            const float* br = bias_bh + (size_t)(q0 + ty*4 + i) * SS + k0 + tx*4;
            #pragma unroll
            for (int j = 0; j < 4; j++) s[i][j] += br[j];
        }

        __syncthreads();   // everyone done reading Ks before it becomes P

        // Online softmax (rows reduced across the 16 tx lanes)
        #pragma unroll
        for (int i = 0; i < 4; i++) {
            float rm = fmaxf(fmaxf(s[i][0], s[i][1]), fmaxf(s[i][2], s[i][3]));
            #pragma unroll
            for (int off = 8; off >= 1; off >>= 1)
                rm = fmaxf(rm, __shfl_xor_sync(0xffffffffu, rm, off));
            float mn    = fmaxf(m_old[i], rm);
            float alpha = __expf(m_old[i] - mn);
            float rs = 0.0f;
            #pragma unroll
            for (int j = 0; j < 4; j++) {
                float p = __expf(s[i][j] - mn);
                s[i][j] = p;
                rs += p;
            }
            #pragma unroll
            for (int off = 8; off >= 1; off >>= 1)
                rs += __shfl_xor_sync(0xffffffffu, rs, off);
            l[i] = l[i] * alpha + rs;
            m_old[i] = mn;
            #pragma unroll
            for (int d = 0; d < 4; d++) acc[i][d] *= alpha;
        }

        // Write P into Ks buffer
        #pragma unroll
        for (int i = 0; i < 4; i++)
            #pragma unroll
            for (int j = 0; j < 4; j++)
                Ks[(ty*4+i)*KS_STR + tx*4 + j] = s[i][j];
        __syncthreads();

        // acc += P . V
        #pragma unroll 4
        for (int j = 0; j < 64; j++) {
            float pr[4], vr[4];
            #pragma unroll
            for (int i = 0; i < 4; i++) pr[i] = Ks[(ty*4+i)*KS_STR + j];
            #pragma unroll
            for (int d = 0; d < 4; d++) vr[d] = Vs[j*VS_STR + tx*4 + d];
            #pragma unroll
            for (int i = 0; i < 4; i++)
                #pragma unroll
                for (int d = 0; d < 4; d++)
                    acc[i][d] = fmaf(pr[i], vr[d], acc[i][d]);
        }
        __syncthreads();   // before next tile overwrites Ks/Vs
    }

    // Normalize and write ctx back in [B,S,D] layout
    #pragma unroll
    for (int i = 0; i < 4; i++) {
        float inv = 1.0f / l[i];
        float* crow = ctx + (size_t)(b*SS + q0 + ty*4 + i) * DD + h*HD + tx*4;
        float4 o;
        o.x = acc[i][0]*inv; o.y = acc[i][1]*inv;
        o.z = acc[i][2]*inv; o.w = acc[i][3]*inv;
        *(float4*)crow = o;
    }
}

// ---------------------------------------------------------------------------
// Launch
// ---------------------------------------------------------------------------
extern "C" void kernel_launch(void* const* d_in, const int* in_sizes, int n_in,
                              void* d_out, int out_size)
{
    const float* Wk   = (const float*)d_in[0];
    const float* Wo   = (const float*)d_in[1];
    const float* Wq   = (const float*)d_in[2];
    const float* Wv   = (const float*)d_in[3];
    const float* gam1 = (const float*)d_in[4];
    const float* Wi   = (const float*)d_in[5];
    const float* Wo2  = (const float*)d_in[6];
    const float* gam2 = (const float*)d_in[7];
    const float* x    = (const float*)d_in[8];
    const float* bias = (const float*)d_in[9];
    float* out = (float*)d_out;

    float *h, *q, *k, *v, *ctx, *y, *h2, *ff;
    void* p;
    cudaGetSymbolAddress(&p, g_h);   h   = (float*)p;
    cudaGetSymbolAddress(&p, g_q);   q   = (float*)p;
    cudaGetSymbolAddress(&p, g_k);   k   = (float*)p;
    cudaGetSymbolAddress(&p, g_v);   v   = (float*)p;
    cudaGetSymbolAddress(&p, g_ctx); ctx = (float*)p;
    cudaGetSymbolAddress(&p, g_y);   y   = (float*)p;
    cudaGetSymbolAddress(&p, g_h2);  h2  = (float*)p;
    cudaGetSymbolAddress(&p, g_ff);  ff  = (float*)p;

    cudaFuncSetAttribute(attention_kernel,
                         cudaFuncAttributeMaxDynamicSharedMemorySize, ATTN_SMEM);

    // 1) h = rmsnorm(x)
    rmsnorm_kernel<<<NT, 128>>>(x, gam1, h);

    // 2) q/k/v projections
    dim3 gQKV(DD / 128, NT / 128);
    sgemm_nt<0><<<gQKV, 256>>>(h, Wq, nullptr, q, NT, DD, DD);
    sgemm_nt<0><<<gQKV, 256>>>(h, Wk, nullptr, k, NT, DD, DD);
    sgemm_nt<0><<<gQKV, 256>>>(h, Wv, nullptr, v, NT, DD, DD);

    // 3) attention
    attention_kernel<<<dim3(SS / 64, BB * HH), 256, ATTN_SMEM>>>(q, k, v, bias, ctx);

    // 4) y = x + ctx @ Wo^T
    sgemm_nt<2><<<gQKV, 256>>>(ctx, Wo, x, y, NT, DD, DD);

    // 5) h2 = rmsnorm(y)
    rmsnorm_kernel<<<NT, 128>>>(y, gam2, h2);

    // 6) ff = relu(h2 @ Wi^T)
    sgemm_nt<1><<<dim3(DFF / 128, NT / 128), 256>>>(h2, Wi, nullptr, ff, NT, DFF, DD);

    // 7) out = y + ff @ Wo2^T
    sgemm_nt<2><<<dim3(DD / 128, NT / 128), 256>>>(ff, Wo2, y, out, NT, DD, DFF);
}

// round 4
// speedup vs baseline: 1.6720x; 1.6720x over previous
#include <cuda_runtime.h>
#include <cuda_bf16.h>
#include <math.h>
#include <stdint.h>

// Problem constants
#define BB   8
#define SS   1024
#define DD   512
#define HH   8
#define HD   64
#define DFF  2048
#define NT   (BB*SS)      // 8192 tokens
#define EPSV 1e-6f

// ---------------------------------------------------------------------------
// Scratch buffers (device globals; no allocation allowed)
// ---------------------------------------------------------------------------
__device__ float g_h  [NT*DD];
__device__ float g_q  [NT*DD];
__device__ float g_k  [NT*DD];
__device__ float g_v  [NT*DD];
__device__ float g_ctx[NT*DD];
__device__ float g_y  [NT*DD];
__device__ float g_h2 [NT*DD];
__device__ float g_ff [NT*DFF];

// bf16 hi/lo split buffers
__device__ __nv_bfloat16 g_act_hi[NT*DFF];
__device__ __nv_bfloat16 g_act_lo[NT*DFF];
#define WOFF_Q   0
#define WOFF_K   262144
#define WOFF_V   524288
#define WOFF_O   786432
#define WOFF_I   1048576
#define WOFF_O2  2097152
__device__ __nv_bfloat16 g_w_hi[3145728];
__device__ __nv_bfloat16 g_w_lo[3145728];

// ---------------------------------------------------------------------------
// Portable (non-100a) asm helpers: cp.async + ldmatrix + mma.sync
// ---------------------------------------------------------------------------
__device__ __forceinline__ uint32_t smem_u32(const void* p) {
    uint32_t a;
    asm("{ .reg .u64 t; cvta.to.shared.u64 t, %1; cvt.u32.u64 %0, t; }" : "=r"(a) : "l"(p));
    return a;
}
#define CP_ASYNC16(sp, gp) \
    asm volatile("cp.async.cg.shared.global [%0], [%1], 16;" :: "r"(sp), "l"(gp))
#define CP_COMMIT() asm volatile("cp.async.commit_group;" ::: "memory")
#define CP_WAIT(N)  asm volatile("cp.async.wait_group %0;" :: "n"(N) : "memory")

#define LDSM_X4(r0, r1, r2, r3, addr)                                      \
    asm volatile("ldmatrix.sync.aligned.m8n8.x4.shared.b16 {%0,%1,%2,%3}, [%4];" \
        : "=r"(r0), "=r"(r1), "=r"(r2), "=r"(r3) : "r"(addr))

__device__ __forceinline__ void mma_bf16(float* c, const uint32_t* a,
                                         uint32_t b0, uint32_t b1) {
    asm volatile(
        "mma.sync.aligned.m16n8k16.row.col.f32.bf16.bf16.f32 "
        "{%0,%1,%2,%3}, {%4,%5,%6,%7}, {%8,%9}, {%0,%1,%2,%3};"
        : "+f"(c[0]), "+f"(c[1]), "+f"(c[2]), "+f"(c[3])
        : "r"(a[0]), "r"(a[1]), "r"(a[2]), "r"(a[3]), "r"(b0), "r"(b1));
}

// ---------------------------------------------------------------------------
// RMSNorm
// ---------------------------------------------------------------------------
__global__ void rmsnorm_kernel(const float* __restrict__ x,
                               const float* __restrict__ w,
                               float* __restrict__ o)
{
    const int row = blockIdx.x;
    const float4* xr = (const float4*)(x + (size_t)row * DD);
    const float4* wr = (const float4*)w;
    float4 v = xr[threadIdx.x];
    float ss = v.x*v.x + v.y*v.y + v.z*v.z + v.w*v.w;
    #pragma unroll
    for (int off = 16; off >= 1; off >>= 1)
        ss += __shfl_xor_sync(0xffffffffu, ss, off);
    __shared__ float sred[4];
    if ((threadIdx.x & 31) == 0) sred[threadIdx.x >> 5] = ss;
    __syncthreads();
    float tot = sred[0] + sred[1] + sred[2] + sred[3];
    float inv = rsqrtf(tot * (1.0f / DD) + EPSV);
    float4 wv = wr[threadIdx.x];
    float4 out;
    out.x = v.x * wv.x * inv;
    out.y = v.y * wv.y * inv;
    out.z = v.z * wv.z * inv;
    out.w = v.w * wv.w * inv;
    ((float4*)(o + (size_t)row * DD))[threadIdx.x] = out;
}

// ---------------------------------------------------------------------------
// fp32 -> bf16 hi/lo split
// ---------------------------------------------------------------------------
__global__ void split_kernel(const float* __restrict__ x,
                             __nv_bfloat16* __restrict__ hi,
                             __nv_bfloat16* __restrict__ lo, int n)
{
    int i = (blockIdx.x * blockDim.x + threadIdx.x) * 4;
    if (i >= n) return;
    float4 v = *(const float4*)(x + i);
    __nv_bfloat16 h0 = __float2bfloat16(v.x);
    __nv_bfloat16 h1 = __float2bfloat16(v.y);
    __nv_bfloat16 h2 = __float2bfloat16(v.z);
    __nv_bfloat16 h3 = __float2bfloat16(v.w);
    __nv_bfloat16 l0 = __float2bfloat16(v.x - __bfloat162float(h0));
    __nv_bfloat16 l1 = __float2bfloat16(v.y - __bfloat162float(h1));
    __nv_bfloat16 l2 = __float2bfloat16(v.z - __bfloat162float(h2));
    __nv_bfloat16 l3 = __float2bfloat16(v.w - __bfloat162float(h3));
    *(__nv_bfloat162*)(hi + i)     = __nv_bfloat162(h0, h1);
    *(__nv_bfloat162*)(hi + i + 2) = __nv_bfloat162(h2, h3);
    *(__nv_bfloat162*)(lo + i)     = __nv_bfloat162(l0, l1);
    *(__nv_bfloat162*)(lo + i + 2) = __nv_bfloat162(l2, l3);
}

// ---------------------------------------------------------------------------
// bf16x3 HMMA GEMM:  C[M,N] = A[M,K] * Bw[N,K]^T  (+ epilogue)
//   EPI 0: none  1: relu  2: += Res
// CTA 128x128, BK=32 bf16 (64B rows, XOR-16B swizzle), cp.async double buffer.
// 8 warps: warp tile 32(M) x 64(N) = 2x8 m16n8k16 tiles.
// ---------------------------------------------------------------------------
#define TILE8K   8192            // one operand tile: 128 rows * 64 B
#define STAGE_B  (4*TILE8K)      // Ahi|Alo|Bhi|Blo
#define GEMM_SMEM (2*STAGE_B)    // 65536

__device__ __forceinline__ void load_stage(
    const __nv_bfloat16* __restrict__ Ahi, const __nv_bfloat16* __restrict__ Alo,
    const __nv_bfloat16* __restrict__ Bhi, const __nv_bfloat16* __restrict__ Blo,
    int K, int k0, uint32_t sstage, int tid)
{
    const __nv_bfloat16* srcs[4] = { Ahi, Alo, Bhi, Blo };
    #pragma unroll
    for (int t = 0; t < 4; ++t) {
        const __nv_bfloat16* g = srcs[t];
        uint32_t sb = sstage + t * TILE8K;
        #pragma unroll
        for (int i = 0; i < 2; ++i) {
            int idx = tid + i * 256;          // 0..511
            int r = idx >> 2;                 // 0..127
            int c = idx & 3;                  // 16B chunk
            const void* gp = g + (size_t)r * K + k0 + c * 8;
            uint32_t sp = sb + r * 64 + ((c ^ (r & 3)) << 4);
            CP_ASYNC16(sp, gp);
        }
    }
}

template<int EPI>
__global__ void __launch_bounds__(256, 1)
gemm_hmma(const __nv_bfloat16* __restrict__ Ahi, const __nv_bfloat16* __restrict__ Alo,
          const __nv_bfloat16* __restrict__ Bhi, const __nv_bfloat16* __restrict__ Blo,
          const float* __restrict__ Res, float* __restrict__ C,
          int M, int Nn, int K)
{
    extern __shared__ char smc[];
    const uint32_t sb = smem_u32(smc);
    const int tid  = threadIdx.x;
    const int warp = tid >> 5;
    const int lane = tid & 31;
    const int wm = warp & 3;        // 0..3 (M)
    const int wn = warp >> 2;       // 0..1 (N)
    const int bm = blockIdx.y * 128;
    const int bn = blockIdx.x * 128;

    const __nv_bfloat16* AhiG = Ahi + (size_t)bm * K;
    const __nv_bfloat16* AloG = Alo + (size_t)bm * K;
    const __nv_bfloat16* BhiG = Bhi + (size_t)bn * K;
    const __nv_bfloat16* BloG = Blo + (size_t)bn * K;

    float acc[2][8][4];
    #pragma unroll
    for (int i = 0; i < 2; i++)
        #pragma unroll
        for (int j = 0; j < 8; j++)
            #pragma unroll
            for (int r = 0; r < 4; r++) acc[i][j][r] = 0.0f;

    // Precompute ldmatrix lane geometry
    uint32_t a_row64[2], a_msk[2];
    #pragma unroll
    for (int mt = 0; mt < 2; ++mt) {
        int r = wm * 32 + mt * 16 + (lane & 15);
        a_row64[mt] = r * 64;
        a_msk[mt]   = r & 3;
    }
    const uint32_t a_ck = lane >> 4;               // 0/1
    uint32_t b_row64[4], b_msk[4];
    #pragma unroll
    for (int bt = 0; bt < 4; ++bt) {
        int n = wn * 64 + bt * 16 + (lane & 7) + ((lane >> 4) << 3);
        b_row64[bt] = n * 64;
        b_msk[bt]   = n & 3;
    }
    const uint32_t b_ck = (lane >> 3) & 1;         // 0/1

    const int NC = K / 32;
    load_stage(AhiG, AloG, BhiG, BloG, K, 0, sb, tid);
    CP_COMMIT();

    for (int c = 0; c < NC; ++c) {
        if (c + 1 < NC) {
            load_stage(AhiG, AloG, BhiG, BloG, K, (c + 1) * 32,
                       sb + ((c + 1) & 1) * STAGE_B, tid);
            CP_COMMIT();
            CP_WAIT(1);
        } else {
            CP_WAIT(0);
        }
        __syncthreads();

        const uint32_t st = sb + (c & 1) * STAGE_B;
        #pragma unroll
        for (int kh = 0; kh < 2; ++kh) {
            uint32_t ah[2][4], al[2][4];
            #pragma unroll
            for (int mt = 0; mt < 2; ++mt) {
                uint32_t ck  = 2 * kh + a_ck;
                uint32_t off = a_row64[mt] + ((ck ^ a_msk[mt]) << 4);
                LDSM_X4(ah[mt][0], ah[mt][1], ah[mt][2], ah[mt][3], st + off);
                LDSM_X4(al[mt][0], al[mt][1], al[mt][2], al[mt][3], st + TILE8K + off);
            }
            uint32_t bh[4][4], bl[4][4];
            #pragma unroll
            for (int bt = 0; bt < 4; ++bt) {
                uint32_t ck  = 2 * kh + b_ck;
                uint32_t off = b_row64[bt] + ((ck ^ b_msk[bt]) << 4);
                LDSM_X4(bh[bt][0], bh[bt][1], bh[bt][2], bh[bt][3], st + 2 * TILE8K + off);
                LDSM_X4(bl[bt][0], bl[bt][1], bl[bt][2], bl[bt][3], st + 3 * TILE8K + off);
            }
            #pragma unroll
            for (int mt = 0; mt < 2; ++mt) {
                #pragma unroll
                for (int bt = 0; bt < 4; ++bt) {
                    // hi*hi
                    mma_bf16(acc[mt][2*bt+0], ah[mt], bh[bt][0], bh[bt][1]);
                    mma_bf16(acc[mt][2*bt+1], ah[mt], bh[bt][2], bh[bt][3]);
                    // lo*hi
                    mma_bf16(acc[mt][2*bt+0], al[mt], bh[bt][0], bh[bt][1]);
                    mma_bf16(acc[mt][2*bt+1], al[mt], bh[bt][2], bh[bt][3]);
                    // hi*lo
                    mma_bf16(acc[mt][2*bt+0], ah[mt], bl[bt][0], bl[bt][1]);
                    mma_bf16(acc[mt][2*bt+1], ah[mt], bl[bt][2], bl[bt][3]);
                }
            }
        }
        __syncthreads();
    }

    // Epilogue: thread l owns rows (wm*32 + mt*16 + l/4, +8), cols (wn*64 + nt*8 + (l%4)*2)
    const int rbase = bm + wm * 32 + (lane >> 2);
    const int cbase = bn + wn * 64 + (lane & 3) * 2;
    #pragma unroll
    for (int mt = 0; mt < 2; ++mt) {
        #pragma unroll
        for (int nt = 0; nt < 8; ++nt) {
            #pragma unroll
            for (int half = 0; half < 2; ++half) {
                int row = rbase + mt * 16 + half * 8;
                int col = cbase + nt * 8;
                float2 v;
                v.x = acc[mt][nt][half * 2 + 0];
                v.y = acc[mt][nt][half * 2 + 1];
                if (EPI == 1) { v.x = fmaxf(v.x, 0.f); v.y = fmaxf(v.y, 0.f); }
                if (EPI == 2) {
                    float2 r = *(const float2*)&Res[(size_t)row * Nn + col];
                    v.x += r.x; v.y += r.y;
                }
                *(float2*)&C[(size_t)row * Nn + col] = v;
            }
        }
    }
}

// ---------------------------------------------------------------------------
// Flash attention (fp32)
// ---------------------------------------------------------------------------
#define QS_STR 64
#define KS_STR 65
#define VS_STR 64
#define ATTN_SMEM ((64*QS_STR + 64*KS_STR + 64*VS_STR) * 4)

__global__ void __launch_bounds__(256)
attention_kernel(const float* __restrict__ q, const float* __restrict__ k,
                 const float* __restrict__ v, const float* __restrict__ bias,
                 float* __restrict__ ctx)
{
    extern __shared__ float sm[];
    float* Qs = sm;
    float* Ks = sm + 64*QS_STR;
    float* Vs = Ks + 64*KS_STR;

    const int q0 = blockIdx.x * 64;
    const int bh = blockIdx.y;
    const int b  = bh / HH;
    const int h  = bh % HH;
    const int tid = threadIdx.x;
    const int ty = tid >> 4;
    const int tx = tid & 15;

    const float* bias_bh = bias + (size_t)bh * SS * SS;

    #pragma unroll
    for (int i = 0; i < 4; i++) {
        int idx = tid + i * 256;
        int r  = idx >> 4;
        int c4 = (idx & 15) * 4;
        float4 qv = *(const float4*)&q[(size_t)(b*SS + q0 + r) * DD + h*HD + c4];
        *(float4*)&Qs[r*QS_STR + c4] = qv;
    }
    __syncthreads();

    float m_old[4], l[4], acc[4][4];
    #pragma unroll
    for (int i = 0; i < 4; i++) {
        m_old[i] = -1e30f; l[i] = 0.0f;
        #pragma unroll
        for (int j = 0; j < 4; j++) acc[i][j] = 0.0f;
    }

    for (int k0 = 0; k0 < SS; k0 += 64) {
        #pragma unroll
        for (int i = 0; i < 4; i++) {
            int idx = tid + i * 256;
            int r  = idx >> 4;
            int c4 = (idx & 15) * 4;
            float4 kv = *(const float4*)&k[(size_t)(b*SS + k0 + r) * DD + h*HD + c4];
            Ks[r*KS_STR + c4+0] = kv.x; Ks[r*KS_STR + c4+1] = kv.y;
            Ks[r*KS_STR + c4+2] = kv.z; Ks[r*KS_STR + c4+3] = kv.w;
            float4 vv = *(const float4*)&v[(size_t)(b*SS + k0 + r) * DD + h*HD + c4];
            *(float4*)&Vs[r*VS_STR + c4] = vv;
        }
        __syncthreads();

        float s[4][4];
        #pragma unroll
        for (int i = 0; i < 4; i++)
            #pragma unroll
            for (int j = 0; j < 4; j++) s[i][j] = 0.0f;

        #pragma unroll 4
        for (int d = 0; d < HD; d++) {
            float qr[4], kr[4];
            #pragma unroll
            for (int i = 0; i < 4; i++) qr[i] = Qs[(ty*4+i)*QS_STR + d];
            #pragma unroll
            for (int j = 0; j < 4; j++) kr[j] = Ks[(tx*4+j)*KS_STR + d];
            #pragma unroll
            for (int i = 0; i < 4; i++)
                #pragma unroll
                for (int j = 0; j < 4; j++)
                    s[i][j] = fmaf(qr[i], kr[j], s[i][j]);
        }
        #pragma unroll
        for (int i = 0; i < 4; i++) {
            const float* br = bias_bh + (size_t)(q0 + ty*4 + i) * SS + k0 + tx*4;
            #pragma unroll
            for (int j = 0; j < 4; j++) s[i][j] += br[j];
        }

        __syncthreads();

        #pragma unroll
        for (int i = 0; i < 4; i++) {
            float rm = fmaxf(fmaxf(s[i][0], s[i][1]), fmaxf(s[i][2], s[i][3]));
            #pragma unroll
            for (int off = 8; off >= 1; off >>= 1)
                rm = fmaxf(rm, __shfl_xor_sync(0xffffffffu, rm, off));
            float mn    = fmaxf(m_old[i], rm);
            float alpha = __expf(m_old[i] - mn);
            float rs = 0.0f;
            #pragma unroll
            for (int j = 0; j < 4; j++) {
                float p = __expf(s[i][j] - mn);
                s[i][j] = p;
                rs += p;
            }
            #pragma unroll
            for (int off = 8; off >= 1; off >>= 1)
                rs += __shfl_xor_sync(0xffffffffu, rs, off);
            l[i] = l[i] * alpha + rs;
            m_old[i] = mn;
            #pragma unroll
            for (int d = 0; d < 4; d++) acc[i][d] *= alpha;
        }

        #pragma unroll
        for (int i = 0; i < 4; i++)
            #pragma unroll
            for (int j = 0; j < 4; j++)
                Ks[(ty*4+i)*KS_STR + tx*4 + j] = s[i][j];
        __syncthreads();

        #pragma unroll 4
        for (int j = 0; j < 64; j++) {
            float pr[4], vr[4];
            #pragma unroll
            for (int i = 0; i < 4; i++) pr[i] = Ks[(ty*4+i)*KS_STR + j];
            #pragma unroll
            for (int d = 0; d < 4; d++) vr[d] = Vs[j*VS_STR + tx*4 + d];
            #pragma unroll
            for (int i = 0; i < 4; i++)
                #pragma unroll
                for (int d = 0; d < 4; d++)
                    acc[i][d] = fmaf(pr[i], vr[d], acc[i][d]);
        }
        __syncthreads();
    }

    #pragma unroll
    for (int i = 0; i < 4; i++) {
        float inv = 1.0f / l[i];
        float* crow = ctx + (size_t)(b*SS + q0 + ty*4 + i) * DD + h*HD + tx*4;
        float4 o;
        o.x = acc[i][0]*inv; o.y = acc[i][1]*inv;
        o.z = acc[i][2]*inv; o.w = acc[i][3]*inv;
        *(float4*)crow = o;
    }
}

// ---------------------------------------------------------------------------
// Launch
// ---------------------------------------------------------------------------
extern "C" void kernel_launch(void* const* d_in, const int* in_sizes, int n_in,
                              void* d_out, int out_size)
{
    const float* Wk   = (const float*)d_in[0];
    const float* Wo   = (const float*)d_in[1];
    const float* Wq   = (const float*)d_in[2];
    const float* Wv   = (const float*)d_in[3];
    const float* gam1 = (const float*)d_in[4];
    const float* Wi   = (const float*)d_in[5];
    const float* Wo2  = (const float*)d_in[6];
    const float* gam2 = (const float*)d_in[7];
    const float* x    = (const float*)d_in[8];
    const float* bias = (const float*)d_in[9];
    float* out = (float*)d_out;

    float *h, *q, *k, *v, *ctx, *y, *h2, *ff;
    __nv_bfloat16 *ahi, *alo, *whi, *wlo;
    void* p;
    cudaGetSymbolAddress(&p, g_h);      h   = (float*)p;
    cudaGetSymbolAddress(&p, g_q);      q   = (float*)p;
    cudaGetSymbolAddress(&p, g_k);      k   = (float*)p;
    cudaGetSymbolAddress(&p, g_v);      v   = (float*)p;
    cudaGetSymbolAddress(&p, g_ctx);    ctx = (float*)p;
    cudaGetSymbolAddress(&p, g_y);      y   = (float*)p;
    cudaGetSymbolAddress(&p, g_h2);     h2  = (float*)p;
    cudaGetSymbolAddress(&p, g_ff);     ff  = (float*)p;
    cudaGetSymbolAddress(&p, g_act_hi); ahi = (__nv_bfloat16*)p;
    cudaGetSymbolAddress(&p, g_act_lo); alo = (__nv_bfloat16*)p;
    cudaGetSymbolAddress(&p, g_w_hi);   whi = (__nv_bfloat16*)p;
    cudaGetSymbolAddress(&p, g_w_lo);   wlo = (__nv_bfloat16*)p;

    cudaFuncSetAttribute(attention_kernel,
                         cudaFuncAttributeMaxDynamicSharedMemorySize, ATTN_SMEM);
    cudaFuncSetAttribute(gemm_hmma<0>,
                         cudaFuncAttributeMaxDynamicSharedMemorySize, GEMM_SMEM);
    cudaFuncSetAttribute(gemm_hmma<1>,
                         cudaFuncAttributeMaxDynamicSharedMemorySize, GEMM_SMEM);
    cudaFuncSetAttribute(gemm_hmma<2>,
                         cudaFuncAttributeMaxDynamicSharedMemorySize, GEMM_SMEM);

    // Weight splits (bf16 hi/lo)
    split_kernel<<<DD*DD/1024, 256>>>(Wq,  whi + WOFF_Q,  wlo + WOFF_Q,  DD*DD);
    split_kernel<<<DD*DD/1024, 256>>>(Wk,  whi + WOFF_K,  wlo + WOFF_K,  DD*DD);
    split_kernel<<<DD*DD/1024, 256>>>(Wv,  whi + WOFF_V,  wlo + WOFF_V,  DD*DD);
    split_kernel<<<DD*DD/1024, 256>>>(Wo,  whi + WOFF_O,  wlo + WOFF_O,  DD*DD);
    split_kernel<<<DFF*DD/1024, 256>>>(Wi,  whi + WOFF_I,  wlo + WOFF_I,  DFF*DD);
    split_kernel<<<DD*DFF/1024, 256>>>(Wo2, whi + WOFF_O2, wlo + WOFF_O2, DD*DFF);

    // 1) h = rmsnorm(x); split
    rmsnorm_kernel<<<NT, 128>>>(x, gam1, h);
    split_kernel<<<NT*DD/1024, 256>>>(h, ahi, alo, NT*DD);

    // 2) q/k/v projections (HMMA bf16x3)
    dim3 gDD(DD/128, NT/128);
    gemm_hmma<0><<<gDD, 256, GEMM_SMEM>>>(ahi, alo, whi + WOFF_Q, wlo + WOFF_Q, nullptr, q, NT, DD, DD);
    gemm_hmma<0><<<gDD, 256, GEMM_SMEM>>>(ahi, alo, whi + WOFF_K, wlo + WOFF_K, nullptr, k, NT, DD, DD);
    gemm_hmma<0><<<gDD, 256, GEMM_SMEM>>>(ahi, alo, whi + WOFF_V, wlo + WOFF_V, nullptr, v, NT, DD, DD);

    // 3) attention
    attention_kernel<<<dim3(SS / 64, BB * HH), 256, ATTN_SMEM>>>(q, k, v, bias, ctx);

    // 4) y = x + ctx @ Wo^T
    split_kernel<<<NT*DD/1024, 256>>>(ctx, ahi, alo, NT*DD);
    gemm_hmma<2><<<gDD, 256, GEMM_SMEM>>>(ahi, alo, whi + WOFF_O, wlo + WOFF_O, x, y, NT, DD, DD);

    // 5) h2 = rmsnorm(y); split
    rmsnorm_kernel<<<NT, 128>>>(y, gam2, h2);
    split_kernel<<<NT*DD/1024, 256>>>(h2, ahi, alo, NT*DD);

    // 6) ff = relu(h2 @ Wi^T)
    gemm_hmma<1><<<dim3(DFF/128, NT/128), 256, GEMM_SMEM>>>(ahi, alo, whi + WOFF_I, wlo + WOFF_I, nullptr, ff, NT, DFF, DD);

    // 7) out = y + ff @ Wo2^T
    split_kernel<<<NT*DFF/1024, 256>>>(ff, ahi, alo, NT*DFF);
    gemm_hmma<2><<<dim3(DD/128, NT/128), 256, GEMM_SMEM>>>(ahi, alo, whi + WOFF_O2, wlo + WOFF_O2, y, out, NT, DD, DFF);
}